// round 1
// baseline (speedup 1.0000x reference)
#include <cuda_runtime.h>
#include <cstdint>

#define BB 128
#define TT 784
#define HH 256
#define LL 20
#define CC 10

// Scratch (device globals: allocation-free per harness rules)
__device__ float g_xp[(size_t)BB * TT * HH];   // per-layer input projection [B*T, H]
__device__ float g_h [(size_t)BB * TT * HH];   // per-layer hidden output   [B*T, H]
__device__ float g_WhT[(size_t)LL * HH * HH];  // W_hh transposed per layer: Wt[l][k][j] = W_hh[l][j][k]

// ---------------------------------------------------------------------------
// Transpose all W_hh layers so the scan's inner loop reads coalesced columns.
// grid (8,8,L), block (32,8)
// ---------------------------------------------------------------------------
__global__ void transpose_whh(const float* __restrict__ W) {
    __shared__ float ts[32][33];
    int l  = blockIdx.z;
    int tx = threadIdx.x, ty = threadIdx.y;
    const float* Wl  = W      + (size_t)l * HH * HH;
    float*       Wtl = g_WhT  + (size_t)l * HH * HH;
    int kb = blockIdx.x * 32;   // k tile (source col)
    int jb = blockIdx.y * 32;   // j tile (source row)
#pragma unroll
    for (int i = 0; i < 32; i += 8)
        ts[ty + i][tx] = Wl[(size_t)(jb + ty + i) * HH + kb + tx];
    __syncthreads();
#pragma unroll
    for (int i = 0; i < 32; i += 8)
        Wtl[(size_t)(kb + ty + i) * HH + jb + tx] = ts[tx][ty + i];
}

// ---------------------------------------------------------------------------
// Layer-0 projection: xp[b,t,h] = x[b,t,0]*W_ih0[h,0] + b_ih0[h]  (I==1)
// grid B*T, block H
// ---------------------------------------------------------------------------
__global__ void proj0_kernel(const float* __restrict__ x,
                             const float* __restrict__ W0,
                             const float* __restrict__ b0) {
    int row = blockIdx.x;
    int j   = threadIdx.x;
    g_xp[(size_t)row * HH + j] = x[row] * W0[j] + b0[j];
}

// ---------------------------------------------------------------------------
// Projection GEMM for layers 1..L-1:
//   g_xp[row, n] = sum_k g_h[row, k] * W_ih[l][n, k] + b_ih[l][n]
// Tiles 128x128, K-tile 16, 256 threads, 8x8 per thread.
// grid (784, 2)
// ---------------------------------------------------------------------------
__global__ __launch_bounds__(256) void proj_kernel(const float* __restrict__ Wih,
                                                   const float* __restrict__ bih,
                                                   int l) {
    const float* A    = g_h;
    const float* Bw   = Wih + (size_t)l * HH * HH;
    const float* bias = bih + (size_t)l * HH;
    float*       Cout = g_xp;

    int tid = threadIdx.x;
    int tx  = tid & 15;       // N direction (8 cols each)
    int ty  = tid >> 4;       // M direction (8 rows each)
    int r0  = blockIdx.x * 128;
    int c0  = blockIdx.y * 128;

    __shared__ float Ash[128][17];   // [m][k] padded
    __shared__ float Bsh[16][132];   // [k][n] padded

    float acc[8][8];
#pragma unroll
    for (int i = 0; i < 8; i++)
#pragma unroll
        for (int j = 0; j < 8; j++) acc[i][j] = 0.0f;

    for (int kt = 0; kt < HH; kt += 16) {
        // Load A tile [128 rows][16 k]
#pragma unroll
        for (int p = 0; p < 8; p++) {
            int f = tid + p * 256;        // 0..2047
            int m = f >> 4;
            int k = f & 15;
            Ash[m][k] = A[(size_t)(r0 + m) * HH + kt + k];
        }
        // Load B tile [128 n][16 k] into [k][n]
#pragma unroll
        for (int p = 0; p < 8; p++) {
            int f = tid + p * 256;
            int n = f >> 4;
            int k = f & 15;
            Bsh[k][n] = Bw[(size_t)(c0 + n) * HH + kt + k];
        }
        __syncthreads();
#pragma unroll
        for (int kk = 0; kk < 16; kk++) {
            float a[8], b[8];
#pragma unroll
            for (int i = 0; i < 8; i++) a[i] = Ash[ty * 8 + i][kk];
            float4 bv0 = *(const float4*)&Bsh[kk][tx * 8];
            float4 bv1 = *(const float4*)&Bsh[kk][tx * 8 + 4];
            b[0] = bv0.x; b[1] = bv0.y; b[2] = bv0.z; b[3] = bv0.w;
            b[4] = bv1.x; b[5] = bv1.y; b[6] = bv1.z; b[7] = bv1.w;
#pragma unroll
            for (int i = 0; i < 8; i++)
#pragma unroll
                for (int j = 0; j < 8; j++)
                    acc[i][j] = fmaf(a[i], b[j], acc[i][j]);
        }
        __syncthreads();
    }

    float bj[8];
#pragma unroll
    for (int j = 0; j < 8; j++) bj[j] = bias[c0 + tx * 8 + j];
#pragma unroll
    for (int i = 0; i < 8; i++) {
        int row = r0 + ty * 8 + i;
#pragma unroll
        for (int j = 0; j < 8; j++)
            Cout[(size_t)row * HH + c0 + tx * 8 + j] = acc[i][j] + bj[j];
    }
}

// ---------------------------------------------------------------------------
// Recurrent scan for one layer. One CTA per 2 batch samples (grid 64),
// thread j owns output column j. Wt is transposed so the k-loop is coalesced.
//   h_t[j] = relu(xp[t,j] + sum_k Wt[k,j]*h_{t-1}[k] + b[j])
// ---------------------------------------------------------------------------
__global__ __launch_bounds__(256) void scan_kernel(const float* __restrict__ bhh,
                                                   int l) {
    const float* Wt   = g_WhT + (size_t)l * HH * HH;
    const float* bias = bhh   + (size_t)l * HH;

    int j  = threadIdx.x;
    int b0 = blockIdx.x * 2;
    int b1 = b0 + 1;

    __shared__ float2 hbuf[2][HH];
    hbuf[0][j] = make_float2(0.0f, 0.0f);
    float bj = bias[j];

    const float* xr0 = g_xp + (size_t)b0 * TT * HH + j;
    const float* xr1 = g_xp + (size_t)b1 * TT * HH + j;
    float*       ho0 = g_h  + (size_t)b0 * TT * HH + j;
    float*       ho1 = g_h  + (size_t)b1 * TT * HH + j;
    __syncthreads();

    for (int t = 0; t < TT; t++) {
        float a0 = xr0[0] + bj;
        float a1 = xr1[0] + bj;
        const float2* hp = hbuf[t & 1];
#pragma unroll 8
        for (int k = 0; k < HH; k++) {
            float  w  = Wt[(size_t)k * HH + j];
            float2 hk = hp[k];
            a0 = fmaf(w, hk.x, a0);
            a1 = fmaf(w, hk.y, a1);
        }
        a0 = fmaxf(a0, 0.0f);
        a1 = fmaxf(a1, 0.0f);
        hbuf[(t & 1) ^ 1][j] = make_float2(a0, a1);
        ho0[0] = a0;
        ho1[0] = a1;
        xr0 += HH; xr1 += HH; ho0 += HH; ho1 += HH;
        __syncthreads();
    }
}

// ---------------------------------------------------------------------------
// Final FC: out[b,c] = sum_k h[b,T-1,k]*W_fc[c,k] + b_fc[c]
// grid B, block H
// ---------------------------------------------------------------------------
__global__ void fc_kernel(const float* __restrict__ Wfc,
                          const float* __restrict__ bfc,
                          float* __restrict__ out) {
    int b   = blockIdx.x;
    int tid = threadIdx.x;
    __shared__ float red[8];
    float hv = g_h[((size_t)b * TT + (TT - 1)) * HH + tid];
#pragma unroll
    for (int c = 0; c < CC; c++) {
        float p = hv * Wfc[(size_t)c * HH + tid];
#pragma unroll
        for (int o = 16; o > 0; o >>= 1)
            p += __shfl_down_sync(0xffffffffu, p, o);
        if ((tid & 31) == 0) red[tid >> 5] = p;
        __syncthreads();
        if (tid == 0) {
            float s = 0.0f;
#pragma unroll
            for (int w = 0; w < 8; w++) s += red[w];
            out[b * CC + c] = s + bfc[c];
        }
        __syncthreads();
    }
}

// ---------------------------------------------------------------------------
extern "C" void kernel_launch(void* const* d_in, const int* in_sizes, int n_in,
                              void* d_out, int out_size) {
    const float* x      = (const float*)d_in[0];
    const float* W_ih0  = (const float*)d_in[1];
    const float* b_ih0  = (const float*)d_in[2];
    const float* W_ih   = (const float*)d_in[3];
    const float* b_ih   = (const float*)d_in[4];
    const float* W_hh   = (const float*)d_in[5];
    const float* b_hh   = (const float*)d_in[6];
    const float* W_fc   = (const float*)d_in[7];
    const float* b_fc   = (const float*)d_in[8];
    float*       out    = (float*)d_out;

    transpose_whh<<<dim3(8, 8, LL), dim3(32, 8)>>>(W_hh);
    proj0_kernel<<<BB * TT, HH>>>(x, W_ih0, b_ih0);

    for (int l = 0; l < LL; l++) {
        scan_kernel<<<BB / 2, HH>>>(b_hh, l);
        if (l < LL - 1)
            proj_kernel<<<dim3((BB * TT) / 128, HH / 128), 256>>>(W_ih, b_ih, l);
    }

    fc_kernel<<<BB, HH>>>(W_fc, b_fc, out);
}

// round 2
// speedup vs baseline: 6.3541x; 6.3541x over previous
#include <cuda_runtime.h>
#include <cstdint>

#define BB 128
#define TT 784
#define HH 256
#define LL 20
#define CC 10

// Scratch (device globals: allocation-free per harness rules)
__device__ float g_xp[(size_t)BB * TT * HH];   // per-layer input projection [B*T, H]
__device__ float g_h [(size_t)BB * TT * HH];   // per-layer hidden output   [B*T, H]

// ---------------------------------------------------------------------------
// helpers
// ---------------------------------------------------------------------------
__device__ __forceinline__ uint32_t smem_u32(const void* p) {
    uint32_t a;
    asm("{ .reg .u64 t; cvta.to.shared.u64 t, %1; cvt.u32.u64 %0, t; }"
        : "=r"(a) : "l"(p));
    return a;
}

// packed fp32x2 fma: c = a*b + c   (Blackwell f32x2 pipe, PTX-only)
__device__ __forceinline__ void ffma2(float2& c, float2 a, float2 b) {
    union U { float2 f; unsigned long long u; };
    U A, Bv, C;
    A.f = a; Bv.f = b; C.f = c;
    asm("fma.rn.f32x2 %0, %1, %2, %3;"
        : "=l"(C.u) : "l"(A.u), "l"(Bv.u), "l"(C.u));
    c = C.f;
}

// ---------------------------------------------------------------------------
// Layer-0 projection: xp[b,t,h] = x[b,t,0]*W_ih0[h,0] + b_ih0[h]  (I==1)
// ---------------------------------------------------------------------------
__global__ void proj0_kernel(const float* __restrict__ x,
                             const float* __restrict__ W0,
                             const float* __restrict__ b0) {
    int row = blockIdx.x;
    int j   = threadIdx.x;
    g_xp[(size_t)row * HH + j] = x[row] * W0[j] + b0[j];
}

// ---------------------------------------------------------------------------
// Projection GEMM (unchanged: measured 84% of fp32 FFMA peak)
//   g_xp[row, n] = sum_k g_h[row, k] * W_ih[l][n, k] + b_ih[l][n]
// ---------------------------------------------------------------------------
__global__ __launch_bounds__(256) void proj_kernel(const float* __restrict__ Wih,
                                                   const float* __restrict__ bih,
                                                   int l) {
    const float* A    = g_h;
    const float* Bw   = Wih + (size_t)l * HH * HH;
    const float* bias = bih + (size_t)l * HH;
    float*       Cout = g_xp;

    int tid = threadIdx.x;
    int tx  = tid & 15;
    int ty  = tid >> 4;
    int r0  = blockIdx.x * 128;
    int c0  = blockIdx.y * 128;

    __shared__ float Ash[128][17];
    __shared__ float Bsh[16][132];

    float acc[8][8];
#pragma unroll
    for (int i = 0; i < 8; i++)
#pragma unroll
        for (int j = 0; j < 8; j++) acc[i][j] = 0.0f;

    for (int kt = 0; kt < HH; kt += 16) {
#pragma unroll
        for (int p = 0; p < 8; p++) {
            int f = tid + p * 256;
            int m = f >> 4;
            int k = f & 15;
            Ash[m][k] = A[(size_t)(r0 + m) * HH + kt + k];
        }
#pragma unroll
        for (int p = 0; p < 8; p++) {
            int f = tid + p * 256;
            int n = f >> 4;
            int k = f & 15;
            Bsh[k][n] = Bw[(size_t)(c0 + n) * HH + kt + k];
        }
        __syncthreads();
#pragma unroll
        for (int kk = 0; kk < 16; kk++) {
            float a[8], b[8];
#pragma unroll
            for (int i = 0; i < 8; i++) a[i] = Ash[ty * 8 + i][kk];
            float4 bv0 = *(const float4*)&Bsh[kk][tx * 8];
            float4 bv1 = *(const float4*)&Bsh[kk][tx * 8 + 4];
            b[0] = bv0.x; b[1] = bv0.y; b[2] = bv0.z; b[3] = bv0.w;
            b[4] = bv1.x; b[5] = bv1.y; b[6] = bv1.z; b[7] = bv1.w;
#pragma unroll
            for (int i = 0; i < 8; i++)
#pragma unroll
                for (int j = 0; j < 8; j++)
                    acc[i][j] = fmaf(a[i], b[j], acc[i][j]);
        }
        __syncthreads();
    }

    float bj[8];
#pragma unroll
    for (int j = 0; j < 8; j++) bj[j] = bias[c0 + tx * 8 + j];
#pragma unroll
    for (int i = 0; i < 8; i++) {
        int row = r0 + ty * 8 + i;
#pragma unroll
        for (int j = 0; j < 8; j++)
            Cout[(size_t)row * HH + c0 + tx * 8 + j] = acc[i][j] + bj[j];
    }
}

// ---------------------------------------------------------------------------
// Recurrent scan, cluster-of-2 version, W in registers.
//
// Grid: 128 CTAs (64 clusters of 2), 256 threads.
// Cluster = one pair of batch samples (b0, b0+1).
// CTA rank r owns output columns [r*128, r*128+128).
// Thread (j = tid>>1, kh = tid&1) accumulates cols j over k half kh,
// holding W[j_global][kh*128 .. +127] in 32 float4 registers.
// Partials combined via shfl (lanes 2j / 2j+1 adjacent).
// h state (both samples) lives in smem, double-buffered; each CTA writes its
// computed 128 cols into its own AND its peer's buffer via DSMEM, then
// cluster-barriers.
//   h_t[j] = relu(xp[t,j] + sum_k W[j,k]*h_{t-1}[k] + b[j])
// ---------------------------------------------------------------------------
#define HPAD 136      // per-kh-half float stride (16B aligned, bank-shifted)
#define HROW (2*HPAD) // floats per buffer row (272)

__global__ __launch_bounds__(256, 1) __cluster_dims__(2, 1, 1)
void scan_kernel(const float* __restrict__ Whh,
                 const float* __restrict__ bhh,
                 int l) {
    __shared__ __align__(16) float sm_h0[2][HROW];  // sample 0, double-buffered
    __shared__ __align__(16) float sm_h1[2][HROW];  // sample 1

    const int tid  = threadIdx.x;
    const int j    = tid >> 1;          // 0..127 local output col
    const int kh   = tid & 1;           // k half
    const int rank = blockIdx.x & 1;    // cluster rank
    const int peer = rank ^ 1;
    const int pair = blockIdx.x >> 1;   // 0..63
    const int b0   = pair * 2;
    const int b1   = b0 + 1;
    const int jg   = rank * 128 + j;    // global output col

    // ---- load W slice into registers (once per layer) ----
    float4 wv[32];
    {
        const float4* Wrow =
            (const float4*)(Whh + ((size_t)l * HH + jg) * HH + kh * 128);
#pragma unroll
        for (int i = 0; i < 32; i++) wv[i] = Wrow[i];
    }

    // ---- zero h state ----
    for (int i = tid; i < HROW; i += 256) {
        sm_h0[0][i] = 0.0f; sm_h0[1][i] = 0.0f;
        sm_h1[0][i] = 0.0f; sm_h1[1][i] = 0.0f;
    }

    // per-thread smem read bases (k = kh*128 + i  ->  float index kh*HPAD + i)
    const float* hp0base = &sm_h0[0][kh * HPAD];
    const float* hp1base = &sm_h1[0][kh * HPAD];

    // remote (peer CTA) smem base addresses for DSMEM stores
    uint32_t loc0 = smem_u32(&sm_h0[0][0]);
    uint32_t loc1 = smem_u32(&sm_h1[0][0]);
    uint32_t rem0, rem1;
    asm("mapa.shared::cluster.u32 %0, %1, %2;" : "=r"(rem0) : "r"(loc0), "r"(peer));
    asm("mapa.shared::cluster.u32 %0, %1, %2;" : "=r"(rem1) : "r"(loc1), "r"(peer));

    // even-lane finalize state
    float bj = 0.0f;
    const float* xp0 = g_xp + (size_t)b0 * TT * HH + jg;
    const float* xp1 = g_xp + (size_t)b1 * TT * HH + jg;
    float*       ho0 = g_h  + (size_t)b0 * TT * HH + jg;
    float*       ho1 = g_h  + (size_t)b1 * TT * HH + jg;
    if (kh == 0) bj = bhh[l * HH + jg];

    const int slot = rank * HPAD + j;   // where col jg lives in the buffers

    __syncthreads();
    // ensure both CTAs finished zero-init before any peer DSMEM writes
    asm volatile("barrier.cluster.arrive.aligned;" ::: "memory");
    asm volatile("barrier.cluster.wait.aligned;"   ::: "memory");

    int cur = 0;
    for (int t = 0; t < TT; t++) {
        // prefetch xp for this step (even lanes; latency hidden by k-loop)
        float xv0 = 0.0f, xv1 = 0.0f;
        if (kh == 0) { xv0 = xp0[0]; xv1 = xp1[0]; xp0 += HH; xp1 += HH; }

        const float* p0 = hp0base + cur * HROW;
        const float* p1 = hp1base + cur * HROW;

        float2 a0a = {0.f, 0.f}, a0b = {0.f, 0.f};
        float2 a1a = {0.f, 0.f}, a1b = {0.f, 0.f};
#pragma unroll
        for (int ii = 0; ii < 32; ii++) {
            float4 h0 = *(const float4*)(p0 + 4 * ii);  // broadcast (2 addrs/warp)
            float4 h1 = *(const float4*)(p1 + 4 * ii);
            float2 wlo = {wv[ii].x, wv[ii].y};
            float2 whi = {wv[ii].z, wv[ii].w};
            ffma2(a0a, wlo, make_float2(h0.x, h0.y));
            ffma2(a0b, whi, make_float2(h0.z, h0.w));
            ffma2(a1a, wlo, make_float2(h1.x, h1.y));
            ffma2(a1b, whi, make_float2(h1.z, h1.w));
        }
        float s0 = (a0a.x + a0a.y) + (a0b.x + a0b.y);
        float s1 = (a1a.x + a1a.y) + (a1b.x + a1b.y);
        // combine kh=0 / kh=1 partials (adjacent lanes)
        s0 += __shfl_down_sync(0xffffffffu, s0, 1);
        s1 += __shfl_down_sync(0xffffffffu, s1, 1);

        int nxt = cur ^ 1;
        if (kh == 0) {
            float r0 = fmaxf(xv0 + bj + s0, 0.0f);
            float r1 = fmaxf(xv1 + bj + s1, 0.0f);
            // local state
            sm_h0[nxt][slot] = r0;
            sm_h1[nxt][slot] = r1;
            // peer state via DSMEM
            uint32_t off = (uint32_t)(nxt * HROW + slot) * 4u;
            asm volatile("st.shared::cluster.f32 [%0], %1;"
                         :: "r"(rem0 + off), "f"(r0) : "memory");
            asm volatile("st.shared::cluster.f32 [%0], %1;"
                         :: "r"(rem1 + off), "f"(r1) : "memory");
            // global output (consumed by next layer's projection / FC)
            ho0[0] = r0; ho1[0] = r1;
            ho0 += HH;  ho1 += HH;
        }

        // cluster-wide: all h writes (local + DSMEM) visible, all CTAs advance
        asm volatile("barrier.cluster.arrive.aligned;" ::: "memory");
        asm volatile("barrier.cluster.wait.aligned;"   ::: "memory");
        cur = nxt;
    }
}

// ---------------------------------------------------------------------------
// Final FC: out[b,c] = sum_k h[b,T-1,k]*W_fc[c,k] + b_fc[c]
// ---------------------------------------------------------------------------
__global__ void fc_kernel(const float* __restrict__ Wfc,
                          const float* __restrict__ bfc,
                          float* __restrict__ out) {
    int b   = blockIdx.x;
    int tid = threadIdx.x;
    __shared__ float red[8];
    float hv = g_h[((size_t)b * TT + (TT - 1)) * HH + tid];
#pragma unroll
    for (int c = 0; c < CC; c++) {
        float p = hv * Wfc[(size_t)c * HH + tid];
#pragma unroll
        for (int o = 16; o > 0; o >>= 1)
            p += __shfl_down_sync(0xffffffffu, p, o);
        if ((tid & 31) == 0) red[tid >> 5] = p;
        __syncthreads();
        if (tid == 0) {
            float s = 0.0f;
#pragma unroll
            for (int w = 0; w < 8; w++) s += red[w];
            out[b * CC + c] = s + bfc[c];
        }
        __syncthreads();
    }
}

// ---------------------------------------------------------------------------
extern "C" void kernel_launch(void* const* d_in, const int* in_sizes, int n_in,
                              void* d_out, int out_size) {
    const float* x      = (const float*)d_in[0];
    const float* W_ih0  = (const float*)d_in[1];
    const float* b_ih0  = (const float*)d_in[2];
    const float* W_ih   = (const float*)d_in[3];
    const float* b_ih   = (const float*)d_in[4];
    const float* W_hh   = (const float*)d_in[5];
    const float* b_hh   = (const float*)d_in[6];
    const float* W_fc   = (const float*)d_in[7];
    const float* b_fc   = (const float*)d_in[8];
    float*       out    = (float*)d_out;

    proj0_kernel<<<BB * TT, HH>>>(x, W_ih0, b_ih0);

    for (int l = 0; l < LL; l++) {
        scan_kernel<<<BB, 256>>>(W_hh, b_hh, l);
        if (l < LL - 1)
            proj_kernel<<<dim3((BB * TT) / 128, HH / 128), 256>>>(W_ih, b_ih, l);
    }

    fc_kernel<<<BB, HH>>>(W_fc, b_fc, out);
}